// round 1
// baseline (speedup 1.0000x reference)
#include <cuda_runtime.h>
#include <cuda_fp16.h>

#define NC 64
#define ND 128
#define INV_T 20.0f

// Scratch (no allocations allowed): counts, global sum, label-dtype flag.
__device__ int    g_counts[NC];
__device__ double g_sum;
__device__ int    g_is32;

__global__ void k_init() {
    int t = threadIdx.x;
    if (t < NC) g_counts[t] = 0;
    if (t == 0) { g_sum = 0.0; g_is32 = 0; }
}

// Detect whether the label buffer is int32 or int64.
// Read the buffer as int32[n] (always in-bounds for both dtypes).
// If int64: entries at odd indices are the high words of the first n/2
// labels -> all zero (labels < 64). If int32: odd entries are labels,
// some nonzero w.p. 1 - (1/64)^(n/2) ~= 1.
__global__ void k_detect(const int* __restrict__ lab32, int half_n) {
    int i = blockIdx.x * blockDim.x + threadIdx.x;
    int stride = gridDim.x * blockDim.x;
    int found = 0;
    for (; i < half_n; i += stride)
        if (lab32[2 * i + 1] != 0) found = 1;
    if (found) g_is32 = 1;
}

__global__ void k_hist(const void* __restrict__ labv, int n) {
    __shared__ int h[NC];
    int t = threadIdx.x;
    if (t < NC) h[t] = 0;
    __syncthreads();
    int is32 = g_is32;
    const int*       l32 = (const int*)labv;
    const long long* l64 = (const long long*)labv;
    for (int i = blockIdx.x * blockDim.x + t; i < n; i += gridDim.x * blockDim.x) {
        int v = is32 ? l32[i] : (int)l64[i];
        atomicAdd(&h[v], 1);
    }
    __syncthreads();
    if (t < NC) atomicAdd(&g_counts[t], h[t]);
}

// Main kernel: 128 threads = 4 warps, 16 rows/warp -> 64 samples per CTA.
// GEMM 64x64x128 via mma.sync.m16n8k16 f16 -> f32, then fused softplus epilogue.
__global__ __launch_bounds__(128) void k_main(
    const float* __restrict__ f1,
    const float* __restrict__ cen,
    const void*  __restrict__ labv,
    int n)
{
    // Centrals as half, row stride 136 halves = 68 u32 (68 % 32 == 4 ->
    // B-fragment LDS across 8 class-rows x 4 k-words hits 32 distinct banks).
    __shared__ unsigned int Bs[NC * 68];
    __shared__ float scnt[NC];
    __shared__ float bsum;

    int t    = threadIdx.x;
    int lane = t & 31, w = t >> 5;
    int gID  = lane >> 2, tig = lane & 3;

    if (t == 0) bsum = 0.f;
    if (t < NC) scnt[t] = (float)g_counts[t];

    // Load centrals [64 x 128] fp32 -> fp16 smem (coalesced float4).
    for (int idx = t; idx < NC * ND / 4; idx += 128) {
        int row = idx >> 5;   // 32 float4 per row
        int c4  = idx & 31;
        float4 v = ((const float4*)cen)[row * 32 + c4];
        __half2 h0 = __floats2half2_rn(v.x, v.y);
        __half2 h1 = __floats2half2_rn(v.z, v.w);
        Bs[row * 68 + c4 * 2]     = *(unsigned int*)&h0;
        Bs[row * 68 + c4 * 2 + 1] = *(unsigned int*)&h1;
    }

    // A fragments straight from global: each thread owns rows (gID, gID+8)
    // of its warp's 16-row slab; per k-tile the needed halves are contiguous
    // float2 pairs, so every f1 element is read exactly once, 32B-sector full.
    int i0 = blockIdx.x * 64 + w * 16 + gID;
    int i1 = i0 + 8;
    size_t r0 = (size_t)min(i0, n - 1) * ND;
    size_t r1 = (size_t)min(i1, n - 1) * ND;
    unsigned int a[32];
#pragma unroll
    for (int kt = 0; kt < 8; kt++) {
        int k = kt * 16 + tig * 2;
        float2 v0 = *(const float2*)(f1 + r0 + k);
        float2 v1 = *(const float2*)(f1 + r1 + k);
        float2 v2 = *(const float2*)(f1 + r0 + k + 8);
        float2 v3 = *(const float2*)(f1 + r1 + k + 8);
        __half2 h;
        h = __floats2half2_rn(v0.x, v0.y); a[kt * 4 + 0] = *(unsigned int*)&h;
        h = __floats2half2_rn(v1.x, v1.y); a[kt * 4 + 1] = *(unsigned int*)&h;
        h = __floats2half2_rn(v2.x, v2.y); a[kt * 4 + 2] = *(unsigned int*)&h;
        h = __floats2half2_rn(v3.x, v3.y); a[kt * 4 + 3] = *(unsigned int*)&h;
    }
    __syncthreads();

    float acc[8][4];
#pragma unroll
    for (int nt = 0; nt < 8; nt++)
        acc[nt][0] = acc[nt][1] = acc[nt][2] = acc[nt][3] = 0.f;

#pragma unroll
    for (int nt = 0; nt < 8; nt++) {
        unsigned int b[16];
#pragma unroll
        for (int kt = 0; kt < 8; kt++) {
            b[2 * kt]     = Bs[(nt * 8 + gID) * 68 + kt * 8 + tig];
            b[2 * kt + 1] = Bs[(nt * 8 + gID) * 68 + kt * 8 + tig + 4];
        }
#pragma unroll
        for (int kt = 0; kt < 8; kt++) {
            asm volatile(
                "mma.sync.aligned.m16n8k16.row.col.f32.f16.f16.f32 "
                "{%0,%1,%2,%3}, {%4,%5,%6,%7}, {%8,%9}, {%0,%1,%2,%3};\n"
                : "+f"(acc[nt][0]), "+f"(acc[nt][1]), "+f"(acc[nt][2]), "+f"(acc[nt][3])
                : "r"(a[kt * 4 + 0]), "r"(a[kt * 4 + 1]),
                  "r"(a[kt * 4 + 2]), "r"(a[kt * 4 + 3]),
                  "r"(b[2 * kt]), "r"(b[2 * kt + 1]));
        }
    }

    // ---- Epilogue ----
    // acc[nt][0..1]: row gID,   cols nt*8 + tig*2 + {0,1}
    // acc[nt][2..3]: row gID+8, same cols
    bool v0 = i0 < n, v1 = i1 < n;
    int is32 = g_is32;
    const int*       l32 = (const int*)labv;
    const long long* l64 = (const long long*)labv;
    int lab0 = 0, lab1 = 0;
    if (v0) lab0 = is32 ? l32[i0] : (int)l64[i0];
    if (v1) lab1 = is32 ? l32[i1] : (int)l64[i1];

    // Pass 1: extract s_pos (exactly one matching column across the quad).
    float pos0 = 0.f, pos1 = 0.f;
#pragma unroll
    for (int nt = 0; nt < 8; nt++) {
        int c = nt * 8 + tig * 2;
        if (c     == lab0) pos0 = acc[nt][0];
        if (c + 1 == lab0) pos0 = acc[nt][1];
        if (c     == lab1) pos1 = acc[nt][2];
        if (c + 1 == lab1) pos1 = acc[nt][3];
    }
    pos0 += __shfl_xor_sync(0xffffffffu, pos0, 1);
    pos0 += __shfl_xor_sync(0xffffffffu, pos0, 2);
    pos1 += __shfl_xor_sync(0xffffffffu, pos1, 1);
    pos1 += __shfl_xor_sync(0xffffffffu, pos1, 2);

    float n0 = scnt[lab0], n1 = scnt[lab1];
    float logn0 = __logf(n0), logn1 = __logf(n1);

    // Pass 2: sum softplus over present negative classes.
    float s0 = 0.f, s1 = 0.f;
#pragma unroll
    for (int nt = 0; nt < 8; nt++) {
#pragma unroll
        for (int j = 0; j < 2; j++) {
            int c = nt * 8 + tig * 2 + j;
            float cn = scnt[c];
            bool present = cn > 0.f;
            if (present && c != lab0) {
                float y = (acc[nt][j] - pos0) * INV_T + logn0;
                s0 += fmaxf(y, 0.f) + __logf(1.f + __expf(-fabsf(y)));
            }
            if (present && c != lab1) {
                float y = (acc[nt][2 + j] - pos1) * INV_T + logn1;
                s1 += fmaxf(y, 0.f) + __logf(1.f + __expf(-fabsf(y)));
            }
        }
    }
    if (!v0) s0 = 0.f;
    if (!v1) s1 = 0.f;
    s0 += __shfl_xor_sync(0xffffffffu, s0, 1);
    s0 += __shfl_xor_sync(0xffffffffu, s0, 2);
    s1 += __shfl_xor_sync(0xffffffffu, s1, 1);
    s1 += __shfl_xor_sync(0xffffffffu, s1, 2);

    if (tig == 0) {
        float contrib = (v0 ? s0 / n0 : 0.f) + (v1 ? s1 / n1 : 0.f);
        atomicAdd(&bsum, contrib);
    }
    __syncthreads();
    if (t == 0) atomicAdd(&g_sum, (double)bsum);
}

__global__ void k_final(float* out) {
    out[0] = (float)g_sum;
}

extern "C" void kernel_launch(void* const* d_in, const int* in_sizes, int n_in,
                              void* d_out, int out_size) {
    const float* f1  = (const float*)d_in[0];
    const float* cen = (const float*)d_in[1];
    const void*  lab = d_in[2];
    int n = in_sizes[0] / ND;   // 262144

    k_init<<<1, 64>>>();
    k_detect<<<132, 256>>>((const int*)lab, n / 2);
    k_hist<<<264, 256>>>(lab, n);
    k_main<<<(n + 63) / 64, 128>>>(f1, cen, lab, n);
    k_final<<<1, 1>>>((float*)d_out);
}

// round 2
// speedup vs baseline: 1.2586x; 1.2586x over previous
#include <cuda_runtime.h>
#include <cuda_fp16.h>

#define NC 64
#define ND 128
#define INV_T 20.0f

__device__ int    g_counts[NC];
__device__ double g_sum;
__device__ int    g_is32;

__global__ void k_init() {
    int t = threadIdx.x;
    if (t < NC) g_counts[t] = 0;
    if (t == 0) { g_sum = 0.0; g_is32 = 0; }
}

// Label dtype sniff: interpret buffer as int32[2*half_n]; for int64 labels
// (<64) every odd word is a zero high-word. Any nonzero odd word => int32.
__global__ void k_detect(const int* __restrict__ lab32, int half_n) {
    int i = blockIdx.x * blockDim.x + threadIdx.x;
    int stride = gridDim.x * blockDim.x;
    int found = 0;
    for (; i < half_n; i += stride)
        if (lab32[2 * i + 1] != 0) found = 1;
    if (found) g_is32 = 1;
}

__global__ void k_hist(const void* __restrict__ labv, int n) {
    __shared__ int h[NC];
    int t = threadIdx.x;
    if (t < NC) h[t] = 0;
    __syncthreads();
    int is32 = g_is32;
    const int*       l32 = (const int*)labv;
    const long long* l64 = (const long long*)labv;
    for (int i = blockIdx.x * blockDim.x + t; i < n; i += gridDim.x * blockDim.x) {
        int v = is32 ? l32[i] : (int)l64[i];
        atomicAdd(&h[v], 1);
    }
    __syncthreads();
    if (t < NC) atomicAdd(&g_counts[t], h[t]);
}

#define MMA4(d, a0, a1, a2, a3, b0, b1)                                        \
    asm volatile(                                                              \
        "mma.sync.aligned.m16n8k16.row.col.f32.f16.f16.f32 "                   \
        "{%0,%1,%2,%3}, {%4,%5,%6,%7}, {%8,%9}, {%0,%1,%2,%3};\n"              \
        : "+f"(d[0]), "+f"(d[1]), "+f"(d[2]), "+f"(d[3])                       \
        : "r"(a0), "r"(a1), "r"(a2), "r"(a3), "r"(b0), "r"(b1))

// 256 threads = 8 warps, 16 rows/warp -> 128 rows/CTA. K split in 2 halves.
__global__ __launch_bounds__(256, 4) void k_main(
    const float* __restrict__ f1,
    const float* __restrict__ cen,
    const void*  __restrict__ labv,
    int n)
{
    // half storage, row stride 68 u32 (= 272B): 8-row LDSM groups land on
    // 32 distinct banks (68 mod 32 == 4).
    __shared__ unsigned int Bs[NC * 68];
    __shared__ float scnt[NC];
    __shared__ float fmask[NC];
    __shared__ float bsum;

    int t    = threadIdx.x;
    int lane = t & 31, w = t >> 5;
    int gID  = lane >> 2, tig = lane & 3;

    if (t == 0) bsum = 0.f;
    if (t < NC) {
        float c = (float)g_counts[t];
        scnt[t]  = c;
        fmask[t] = c > 0.f ? 1.f : 0.f;
    }

    // Fill B smem: fp32 -> fp16, coalesced float4.
    for (int idx = t; idx < NC * 32; idx += 256) {
        int row = idx >> 5, c4 = idx & 31;
        float4 v = ((const float4*)cen)[idx];
        __half2 h0 = __floats2half2_rn(v.x, v.y);
        __half2 h1 = __floats2half2_rn(v.z, v.w);
        Bs[row * 68 + c4 * 2]     = *(unsigned int*)&h0;
        Bs[row * 68 + c4 * 2 + 1] = *(unsigned int*)&h1;
    }

    int i0 = blockIdx.x * 128 + w * 16 + gID;
    int i1 = i0 + 8;
    const float* p0 = f1 + (size_t)min(i0, n - 1) * ND;
    const float* p1 = f1 + (size_t)min(i1, n - 1) * ND;

    // ldmatrix lane base: lanes 0-7 tile0, 8-15 tile1, 16-23 tile2, 24-31 tile3.
    unsigned sbase = (unsigned)__cvta_generic_to_shared(Bs)
                   + (lane & 7) * 272 + (lane >> 3) * 16;

    __syncthreads();

    float acc[8][4];
#pragma unroll
    for (int nt = 0; nt < 8; nt++)
        acc[nt][0] = acc[nt][1] = acc[nt][2] = acc[nt][3] = 0.f;

#pragma unroll
    for (int h = 0; h < 2; h++) {
        // A fragments straight from global (each element read exactly once).
        unsigned a[16];
        const float* q0 = p0 + h * 64;
        const float* q1 = p1 + h * 64;
#pragma unroll
        for (int kt = 0; kt < 4; kt++) {
            int k = kt * 16 + tig * 2;
            float2 v0 = *(const float2*)(q0 + k);
            float2 v1 = *(const float2*)(q1 + k);
            float2 v2 = *(const float2*)(q0 + k + 8);
            float2 v3 = *(const float2*)(q1 + k + 8);
            __half2 hh;
            hh = __floats2half2_rn(v0.x, v0.y); a[kt * 4 + 0] = *(unsigned int*)&hh;
            hh = __floats2half2_rn(v1.x, v1.y); a[kt * 4 + 1] = *(unsigned int*)&hh;
            hh = __floats2half2_rn(v2.x, v2.y); a[kt * 4 + 2] = *(unsigned int*)&hh;
            hh = __floats2half2_rn(v3.x, v3.y); a[kt * 4 + 3] = *(unsigned int*)&hh;
        }
#pragma unroll
        for (int nt = 0; nt < 8; nt++) {
#pragma unroll
            for (int p = 0; p < 2; p++) {
                unsigned b0, b1, b2, b3;
                unsigned addr = sbase + nt * 2176 + h * 128 + p * 64;
                asm volatile(
                    "ldmatrix.sync.aligned.m8n8.x4.shared.b16 {%0,%1,%2,%3}, [%4];\n"
                    : "=r"(b0), "=r"(b1), "=r"(b2), "=r"(b3) : "r"(addr));
                MMA4(acc[nt], a[(2 * p) * 4 + 0], a[(2 * p) * 4 + 1],
                              a[(2 * p) * 4 + 2], a[(2 * p) * 4 + 3], b0, b1);
                MMA4(acc[nt], a[(2 * p + 1) * 4 + 0], a[(2 * p + 1) * 4 + 1],
                              a[(2 * p + 1) * 4 + 2], a[(2 * p + 1) * 4 + 3], b2, b3);
            }
        }
    }

    // ---- Epilogue ----
    // acc[nt][0..1]: row gID  cols nt*8 + tig*2 + {0,1}; [2..3]: row gID+8.
    bool v0 = i0 < n, v1 = i1 < n;
    int is32 = g_is32;
    int lab0 = 0, lab1 = 0;
    if (v0) lab0 = is32 ? ((const int*)labv)[i0] : (int)((const long long*)labv)[i0];
    if (v1) lab1 = is32 ? ((const int*)labv)[i1] : (int)((const long long*)labv)[i1];

    float pos0 = 0.f, pos1 = 0.f;
#pragma unroll
    for (int nt = 0; nt < 8; nt++) {
        int c = nt * 8 + tig * 2;
        if (c     == lab0) pos0 = acc[nt][0];
        if (c + 1 == lab0) pos0 = acc[nt][1];
        if (c     == lab1) pos1 = acc[nt][2];
        if (c + 1 == lab1) pos1 = acc[nt][3];
    }
    pos0 += __shfl_xor_sync(0xffffffffu, pos0, 1);
    pos0 += __shfl_xor_sync(0xffffffffu, pos0, 2);
    pos1 += __shfl_xor_sync(0xffffffffu, pos1, 1);
    pos1 += __shfl_xor_sync(0xffffffffu, pos1, 2);

    float n0 = scnt[lab0], n1 = scnt[lab1];
    float pp0 = __logf(n0) - pos0 * INV_T;
    float pp1 = __logf(n1) - pos1 * INV_T;

    // Sum softplus over ALL present classes (own class subtracted after).
    float s0 = 0.f, s1 = 0.f;
#pragma unroll
    for (int nt = 0; nt < 8; nt++) {
        int c = nt * 8 + tig * 2;
        float ma = fmask[c], mb = fmask[c + 1];
        float y, sp;
        y  = fmaf(acc[nt][0], INV_T, pp0);
        sp = fmaxf(y, 0.f) + __logf(1.f + __expf(-fabsf(y)));
        s0 = fmaf(ma, sp, s0);
        y  = fmaf(acc[nt][1], INV_T, pp0);
        sp = fmaxf(y, 0.f) + __logf(1.f + __expf(-fabsf(y)));
        s0 = fmaf(mb, sp, s0);
        y  = fmaf(acc[nt][2], INV_T, pp1);
        sp = fmaxf(y, 0.f) + __logf(1.f + __expf(-fabsf(y)));
        s1 = fmaf(ma, sp, s1);
        y  = fmaf(acc[nt][3], INV_T, pp1);
        sp = fmaxf(y, 0.f) + __logf(1.f + __expf(-fabsf(y)));
        s1 = fmaf(mb, sp, s1);
    }
    s0 += __shfl_xor_sync(0xffffffffu, s0, 1);
    s0 += __shfl_xor_sync(0xffffffffu, s0, 2);
    s1 += __shfl_xor_sync(0xffffffffu, s1, 1);
    s1 += __shfl_xor_sync(0xffffffffu, s1, 2);

    if (tig == 0) {
        float contrib = 0.f;
        // Own-class term included above = softplus(log n) = log(1+n); remove.
        if (v0) contrib += (s0 - __logf(1.f + n0)) / n0;
        if (v1) contrib += (s1 - __logf(1.f + n1)) / n1;
        atomicAdd(&bsum, contrib);
    }
    __syncthreads();
    if (t == 0) atomicAdd(&g_sum, (double)bsum);
}

__global__ void k_final(float* out) {
    out[0] = (float)g_sum;
}

extern "C" void kernel_launch(void* const* d_in, const int* in_sizes, int n_in,
                              void* d_out, int out_size) {
    const float* f1  = (const float*)d_in[0];
    const float* cen = (const float*)d_in[1];
    const void*  lab = d_in[2];
    int n = in_sizes[0] / ND;

    k_init<<<1, 64>>>();
    k_detect<<<132, 256>>>((const int*)lab, n / 2);
    k_hist<<<264, 256>>>(lab, n);
    k_main<<<(n + 127) / 128, 256>>>(f1, cen, lab, n);
    k_final<<<1, 1>>>((float*)d_out);
}